// round 4
// baseline (speedup 1.0000x reference)
#include <cuda_runtime.h>
#include <math.h>
#include <stdint.h>

#define K_CLUSTERS   20
#define CLUSTER_SIZE 5000
#define HIDDEN       256
#define N_ROWS       (K_CLUSTERS * CLUSTER_SIZE)   // 100000

// ---- scratch (__device__ globals: no allocation allowed) ----
__device__ float g_cluster_sum[K_CLUSTERS][HIDDEN];
__device__ __align__(16) float g_Wc[K_CLUSTERS][HIDDEN];
__device__ float g_total;
__device__ int   g_idx64;   // 1 if cluster_info is int64, 0 if int32

// Load index i from cluster_info regardless of its storage dtype.
__device__ __forceinline__ int load_idx(const void* ci, int i) {
    if (g_idx64) return (int)((const long long*)ci)[i];
    return ((const int*)ci)[i];
}

// ---------------------------------------------------------------------------
// Kernel A: detect index dtype.
// int64 little-endian values < 2^31 have zero high words: int32-view odd
// positions are all 0. With real int32 data they are random row indices.
// ---------------------------------------------------------------------------
__global__ void k_detect(const int* __restrict__ ci32) {
    int t = threadIdx.x;
    int v = ci32[2 * t + 1];           // positions 1,3,...,511 (< 100000 ints)
    int any_nonzero = __syncthreads_or(v != 0);
    if (t == 0) g_idx64 = any_nonzero ? 0 : 1;
}

// ---------------------------------------------------------------------------
// Kernel 0: zero scratch
// ---------------------------------------------------------------------------
__global__ void k_init() {
    int i = blockIdx.x * blockDim.x + threadIdx.x;
    if (i < K_CLUSTERS * HIDDEN) ((float*)g_cluster_sum)[i] = 0.0f;
    if (i == 0) g_total = 0.0f;
}

// ---------------------------------------------------------------------------
// Kernel 1: per-cluster gather-sum of h_1 rows.
// grid = K_CLUSTERS * CHUNKS blocks, 256 threads (thread t <-> dim t, coalesced)
// ---------------------------------------------------------------------------
#define CHUNKS          40
#define ROWS_PER_CHUNK  (CLUSTER_SIZE / CHUNKS)    // 125

__global__ void k_gather_sum(const float* __restrict__ h1,
                             const void* __restrict__ ci) {
    int k     = blockIdx.x / CHUNKS;
    int chunk = blockIdx.x % CHUNKS;
    int t     = threadIdx.x;

    __shared__ int s_idx[ROWS_PER_CHUNK];
    int base = k * CLUSTER_SIZE + chunk * ROWS_PER_CHUNK;
    if (t < ROWS_PER_CHUNK) s_idx[t] = load_idx(ci, base + t);
    __syncthreads();

    float acc = 0.0f;
    #pragma unroll 5
    for (int r = 0; r < ROWS_PER_CHUNK; ++r) {
        int row = s_idx[r];
        acc += __ldg(h1 + (long long)row * HIDDEN + t);
    }
    atomicAdd(&g_cluster_sum[k][t], acc);
}

// ---------------------------------------------------------------------------
// Kernel 2: c = sigmoid(mean), Wc[k,d] = sum_e W[d,e] * c[k,e]
// grid = K_CLUSTERS blocks, 256 threads (8 warps, warp per output d, coalesced)
// ---------------------------------------------------------------------------
__global__ void k_wc(const float* __restrict__ W) {
    int k = blockIdx.x;
    int t = threadIdx.x;
    __shared__ float c_sh[HIDDEN];
    float m = g_cluster_sum[k][t] * (1.0f / (float)CLUSTER_SIZE);
    c_sh[t] = 1.0f / (1.0f + __expf(-m));
    __syncthreads();

    int lane = t & 31;
    int wid  = t >> 5;
    for (int d = wid; d < HIDDEN; d += 8) {
        const float* wrow = W + d * HIDDEN;
        float acc = 0.0f;
        #pragma unroll
        for (int e = lane; e < HIDDEN; e += 32)
            acc += wrow[e] * c_sh[e];
        #pragma unroll
        for (int o = 16; o; o >>= 1)
            acc += __shfl_xor_sync(0xffffffffu, acc, o);
        if (lane == 0) g_Wc[k][d] = acc;
    }
}

// ---------------------------------------------------------------------------
// Kernel 3: per-row bilinear scores + softplus, reduced to one global sum.
// 1 warp per (k, n) row-pair; 8 warps / block; grid = N_ROWS/8 = 12500 blocks.
// ---------------------------------------------------------------------------
__device__ __forceinline__ float softplus_f(float x) {
    // log(1 + e^x), numerically stable
    return fmaxf(x, 0.0f) + log1pf(__expf(-fabsf(x)));
}
__device__ __forceinline__ float dot4(float4 a, float4 b) {
    return a.x * b.x + a.y * b.y + a.z * b.z + a.w * b.w;
}

__global__ void k_scores(const float* __restrict__ h1,
                         const float* __restrict__ h2,
                         const void* __restrict__ ci,
                         const float* __restrict__ b_ptr) {
    int w    = blockIdx.x * 8 + (threadIdx.x >> 5);   // global warp id = row id
    int lane = threadIdx.x & 31;

    __shared__ float s_acc;
    if (threadIdx.x == 0) s_acc = 0.0f;
    __syncthreads();

    if (w < N_ROWS) {
        int k = w / CLUSTER_SIZE;
        long long row = (long long)load_idx(ci, w);

        const float4* r1 = (const float4*)(h1 + row * HIDDEN);
        const float4* r2 = (const float4*)(h2 + row * HIDDEN);
        const float4* wc = (const float4*)(&g_Wc[k][0]);

        // 256 floats = 64 float4; lanes cover [lane] and [lane+32]
        float4 c0 = wc[lane], c1 = wc[lane + 32];
        float4 a0 = r1[lane], a1 = r1[lane + 32];
        float4 b0 = r2[lane], b1 = r2[lane + 32];

        float s1 = dot4(a0, c0) + dot4(a1, c1);
        float s2 = dot4(b0, c0) + dot4(b1, c1);
        #pragma unroll
        for (int o = 16; o; o >>= 1) {
            s1 += __shfl_xor_sync(0xffffffffu, s1, o);
            s2 += __shfl_xor_sync(0xffffffffu, s2, o);
        }
        if (lane == 0) {
            float b = __ldg(b_ptr);
            // positives: softplus(-(s1+b)); negatives: softplus(s2+b)
            float loss = softplus_f(-(s1 + b)) + softplus_f(s2 + b);
            atomicAdd(&s_acc, loss);
        }
    }
    __syncthreads();
    if (threadIdx.x == 0) atomicAdd(&g_total, s_acc);
}

// ---------------------------------------------------------------------------
// Kernel 4: finalize
// loss = 0.5/(K*n) * total
// ---------------------------------------------------------------------------
__global__ void k_finalize(float* __restrict__ out) {
    out[0] = 0.5f * g_total / (float)N_ROWS;
}

// ---------------------------------------------------------------------------
extern "C" void kernel_launch(void* const* d_in, const int* in_sizes, int n_in,
                              void* d_out, int out_size) {
    const float* h1 = (const float*)d_in[0];
    const float* h2 = (const float*)d_in[1];
    const void*  ci = d_in[2];
    const float* W  = (const float*)d_in[3];
    const float* b  = (const float*)d_in[4];
    float*      out = (float*)d_out;

    k_detect<<<1, 256>>>((const int*)ci);
    k_init<<<(K_CLUSTERS * HIDDEN + 255) / 256, 256>>>();
    k_gather_sum<<<K_CLUSTERS * CHUNKS, 256>>>(h1, ci);
    k_wc<<<K_CLUSTERS, 256>>>(W);
    k_scores<<<N_ROWS / 8, 256>>>(h1, h2, ci, b);
    k_finalize<<<1, 1>>>(out);
}

// round 5
// speedup vs baseline: 1.1360x; 1.1360x over previous
#include <cuda_runtime.h>
#include <math.h>
#include <stdint.h>

#define K_CLUSTERS   20
#define CLUSTER_SIZE 5000
#define HIDDEN       256
#define N_ROWS       (K_CLUSTERS * CLUSTER_SIZE)   // 100000

// ---- scratch (__device__ globals: no allocation allowed) ----
__device__ float g_cluster_sum[K_CLUSTERS][HIDDEN];
__device__ __align__(16) float g_Wc[K_CLUSTERS][HIDDEN];
__device__ float g_total;
__device__ int   g_idx64;   // 1 if cluster_info is int64, 0 if int32

// Load index i from cluster_info regardless of its storage dtype.
__device__ __forceinline__ int load_idx(const void* ci, int i) {
    if (g_idx64) return (int)((const long long*)ci)[i];
    return ((const int*)ci)[i];
}

// ---------------------------------------------------------------------------
// Kernel A: detect index dtype + zero scratch.
// int64 little-endian values < 2^31 have zero high words: int32-view odd
// positions are all 0. With real int32 data they are random row indices.
// ---------------------------------------------------------------------------
__global__ void k_detect(const int* __restrict__ ci32) {
    int t = threadIdx.x;
    int v = ci32[2 * t + 1];           // positions 1,3,...,511
    int any_nonzero = __syncthreads_or(v != 0);
    if (t == 0) {
        g_idx64 = any_nonzero ? 0 : 1;
        g_total = 0.0f;
    }
}

__global__ void k_init() {
    int i = blockIdx.x * blockDim.x + threadIdx.x;
    if (i < K_CLUSTERS * HIDDEN) ((float*)g_cluster_sum)[i] = 0.0f;
}

// ---------------------------------------------------------------------------
// Kernel 1: per-cluster gather-sum of h_1 rows.
// grid = K_CLUSTERS * CHUNKS blocks, 256 threads (thread t <-> dim t, coalesced)
// ---------------------------------------------------------------------------
#define CHUNKS          40
#define ROWS_PER_CHUNK  (CLUSTER_SIZE / CHUNKS)    // 125

__global__ void k_gather_sum(const float* __restrict__ h1,
                             const void* __restrict__ ci) {
    int k     = blockIdx.x / CHUNKS;
    int chunk = blockIdx.x % CHUNKS;
    int t     = threadIdx.x;

    __shared__ int s_idx[ROWS_PER_CHUNK];
    int base = k * CLUSTER_SIZE + chunk * ROWS_PER_CHUNK;
    if (t < ROWS_PER_CHUNK) s_idx[t] = load_idx(ci, base + t);
    __syncthreads();

    float acc = 0.0f;
    #pragma unroll 5
    for (int r = 0; r < ROWS_PER_CHUNK; ++r) {
        int row = s_idx[r];
        acc += __ldg(h1 + (long long)row * HIDDEN + t);
    }
    atomicAdd(&g_cluster_sum[k][t], acc);
}

// ---------------------------------------------------------------------------
// Kernel 2: Wc[k,d] = sum_e W[d,e] * sigmoid(mean_e)
// grid = 32 blocks x 8 warps: one warp per output dim d (256 warps total).
// Each block computes c[20][256] into shared, each warp reads its W row once.
// ---------------------------------------------------------------------------
__global__ void k_wc(const float* __restrict__ W) {
    __shared__ float c_sh[K_CLUSTERS][HIDDEN];
    int t = threadIdx.x;

    // all 256 threads: compute c (each thread handles 20 elems, coalesced)
    #pragma unroll
    for (int k = 0; k < K_CLUSTERS; ++k) {
        float m = g_cluster_sum[k][t] * (1.0f / (float)CLUSTER_SIZE);
        c_sh[k][t] = 1.0f / (1.0f + __expf(-m));
    }
    __syncthreads();

    int lane = t & 31;
    int wid  = t >> 5;
    int d    = blockIdx.x * 8 + wid;    // this warp's output dim

    // load W row d: 256 elems / 32 lanes = 8 regs, coalesced
    float w[8];
    const float* wrow = W + d * HIDDEN;
    #pragma unroll
    for (int j = 0; j < 8; ++j) w[j] = __ldg(wrow + lane + 32 * j);

    #pragma unroll
    for (int k = 0; k < K_CLUSTERS; ++k) {
        float acc = 0.0f;
        #pragma unroll
        for (int j = 0; j < 8; ++j) acc += w[j] * c_sh[k][lane + 32 * j];
        #pragma unroll
        for (int o = 16; o; o >>= 1)
            acc += __shfl_xor_sync(0xffffffffu, acc, o);
        if (lane == 0) g_Wc[k][d] = acc;
    }
}

// ---------------------------------------------------------------------------
// Kernel 3: per-row bilinear scores + softplus, reduced to one global sum.
// 1 warp per (k, n) row-pair; 8 warps / block; grid = N_ROWS/8 = 12500 blocks.
// 5000 % 8 == 0 -> every block lies entirely within one cluster, so Wc[k]
// is staged once per block into shared.
// ---------------------------------------------------------------------------
__device__ __forceinline__ float softplus_f(float x) {
    return fmaxf(x, 0.0f) + log1pf(__expf(-fabsf(x)));
}
__device__ __forceinline__ float dot4(float4 a, float4 b) {
    return a.x * b.x + a.y * b.y + a.z * b.z + a.w * b.w;
}

#define ROWS_PER_BLOCK 8
#define BLOCKS_PER_CLUSTER (CLUSTER_SIZE / ROWS_PER_BLOCK)   // 625

__global__ void k_scores(const float* __restrict__ h1,
                         const float* __restrict__ h2,
                         const void* __restrict__ ci,
                         const float* __restrict__ b_ptr) {
    int t    = threadIdx.x;
    int lane = t & 31;
    int wid  = t >> 5;
    int w    = blockIdx.x * ROWS_PER_BLOCK + wid;   // global row id
    int k    = blockIdx.x / BLOCKS_PER_CLUSTER;     // whole block same cluster

    __shared__ __align__(16) float wc_sh[HIDDEN];
    __shared__ float s_acc;
    wc_sh[t] = g_Wc[k][t];
    if (t == 0) s_acc = 0.0f;
    __syncthreads();

    long long row = (long long)load_idx(ci, w);

    const float4* r1 = (const float4*)(h1 + row * HIDDEN);
    const float4* r2 = (const float4*)(h2 + row * HIDDEN);
    const float4* wc = (const float4*)wc_sh;

    float4 c0 = wc[lane], c1 = wc[lane + 32];
    float4 a0 = r1[lane], a1 = r1[lane + 32];
    float4 b0 = r2[lane], b1 = r2[lane + 32];

    float s1 = dot4(a0, c0) + dot4(a1, c1);
    float s2 = dot4(b0, c0) + dot4(b1, c1);
    #pragma unroll
    for (int o = 16; o; o >>= 1) {
        s1 += __shfl_xor_sync(0xffffffffu, s1, o);
        s2 += __shfl_xor_sync(0xffffffffu, s2, o);
    }
    if (lane == 0) {
        float b = __ldg(b_ptr);
        float loss = softplus_f(-(s1 + b)) + softplus_f(s2 + b);
        atomicAdd(&s_acc, loss);
    }
    __syncthreads();
    if (t == 0) atomicAdd(&g_total, s_acc);
}

// ---------------------------------------------------------------------------
// Kernel 4: finalize   loss = 0.5/(K*n) * total
// ---------------------------------------------------------------------------
__global__ void k_finalize(float* __restrict__ out) {
    out[0] = 0.5f * g_total / (float)N_ROWS;
}

// ---------------------------------------------------------------------------
extern "C" void kernel_launch(void* const* d_in, const int* in_sizes, int n_in,
                              void* d_out, int out_size) {
    const float* h1 = (const float*)d_in[0];
    const float* h2 = (const float*)d_in[1];
    const void*  ci = d_in[2];
    const float* W  = (const float*)d_in[3];
    const float* b  = (const float*)d_in[4];
    float*      out = (float*)d_out;

    k_detect<<<1, 256>>>((const int*)ci);
    k_init<<<(K_CLUSTERS * HIDDEN + 255) / 256, 256>>>();
    k_gather_sum<<<K_CLUSTERS * CHUNKS, 256>>>(h1, ci);
    k_wc<<<HIDDEN / 8, 256>>>(W);
    k_scores<<<N_ROWS / ROWS_PER_BLOCK, 256>>>(h1, h2, ci, b);
    k_finalize<<<1, 1>>>(out);
}

// round 6
// speedup vs baseline: 1.3141x; 1.1568x over previous
#include <cuda_runtime.h>
#include <math.h>
#include <stdint.h>

#define K_CLUSTERS   20
#define CLUSTER_SIZE 5000
#define HIDDEN       256
#define N_ROWS       (K_CLUSTERS * CLUSTER_SIZE)   // 100000

// ---- scratch (__device__ globals: no allocation allowed) ----
__device__ float g_cluster_sum[K_CLUSTERS][HIDDEN];
__device__ __align__(16) float g_Wc[K_CLUSTERS][HIDDEN];
__device__ float g_total;
__device__ int   g_idx64;   // 1 if cluster_info is int64, 0 if int32

// Load index i from cluster_info regardless of its storage dtype.
__device__ __forceinline__ int load_idx(const void* ci, int i) {
    if (g_idx64) return (int)((const long long*)ci)[i];
    return ((const int*)ci)[i];
}

// ---------------------------------------------------------------------------
// Kernel 0: setup — zero scratch + detect index dtype (block 0 only).
// int64 little-endian values < 2^31 have zero high words: int32-view odd
// positions are all 0. With real int32 data they are random row indices.
// ---------------------------------------------------------------------------
__global__ void k_setup(const int* __restrict__ ci32) {
    int t = threadIdx.x;
    g_cluster_sum[blockIdx.x][t] = 0.0f;
    if (blockIdx.x == 0) {
        int v = ci32[2 * t + 1];           // positions 1,3,...,511
        int any_nonzero = __syncthreads_or(v != 0);
        if (t == 0) {
            g_idx64 = any_nonzero ? 0 : 1;
            g_total = 0.0f;
        }
    }
}

// ---------------------------------------------------------------------------
// Kernel 1: per-cluster gather-sum of h_1 rows.
// grid = K_CLUSTERS * CHUNKS blocks, 256 threads (thread t <-> dim t, coalesced)
// ---------------------------------------------------------------------------
#define CHUNKS          40
#define ROWS_PER_CHUNK  (CLUSTER_SIZE / CHUNKS)    // 125

__global__ void k_gather_sum(const float* __restrict__ h1,
                             const void* __restrict__ ci) {
    int k     = blockIdx.x / CHUNKS;
    int chunk = blockIdx.x % CHUNKS;
    int t     = threadIdx.x;

    __shared__ int s_idx[ROWS_PER_CHUNK];
    int base = k * CLUSTER_SIZE + chunk * ROWS_PER_CHUNK;
    if (t < ROWS_PER_CHUNK) s_idx[t] = load_idx(ci, base + t);
    __syncthreads();

    float acc = 0.0f;
    #pragma unroll 5
    for (int r = 0; r < ROWS_PER_CHUNK; ++r) {
        int row = s_idx[r];
        acc += __ldg(h1 + (long long)row * HIDDEN + t);
    }
    atomicAdd(&g_cluster_sum[k][t], acc);
}

// ---------------------------------------------------------------------------
// Kernel 2: Wc[k,d] = sum_e W[d,e] * sigmoid(mean_e)
// k-major warp-per-output: grid = K_CLUSTERS*32 = 640 blocks x 8 warps.
// Block b: cluster k = b/32, dims d in [ (b%32)*8, +8 ); one warp per d.
// Block computes ONE sigmoid row into shared (cheap), warps dot W rows vs it.
// ---------------------------------------------------------------------------
__global__ void k_wc(const float* __restrict__ W) {
    __shared__ float c_sh[HIDDEN];
    int t    = threadIdx.x;
    int lane = t & 31;
    int wid  = t >> 5;
    int k    = blockIdx.x >> 5;            // /32
    int d    = ((blockIdx.x & 31) << 3) + wid;

    float m = g_cluster_sum[k][t] * (1.0f / (float)CLUSTER_SIZE);
    c_sh[t] = 1.0f / (1.0f + __expf(-m));
    __syncthreads();

    const float* wrow = W + d * HIDDEN;
    float acc = 0.0f;
    #pragma unroll
    for (int j = 0; j < 8; ++j)
        acc += __ldg(wrow + lane + 32 * j) * c_sh[lane + 32 * j];
    #pragma unroll
    for (int o = 16; o; o >>= 1)
        acc += __shfl_xor_sync(0xffffffffu, acc, o);
    if (lane == 0) g_Wc[k][d] = acc;
}

// ---------------------------------------------------------------------------
// Kernel 3: per-row bilinear scores + softplus, reduced to one global sum.
// 1 warp per (k, n) row-pair; 8 warps / block; grid = N_ROWS/8 = 12500 blocks.
// 5000 % 8 == 0 -> every block lies entirely within one cluster, so Wc[k]
// is staged once per block into shared.
// ---------------------------------------------------------------------------
__device__ __forceinline__ float softplus_f(float x) {
    return fmaxf(x, 0.0f) + log1pf(__expf(-fabsf(x)));
}
__device__ __forceinline__ float dot4(float4 a, float4 b) {
    return a.x * b.x + a.y * b.y + a.z * b.z + a.w * b.w;
}

#define ROWS_PER_BLOCK 8
#define BLOCKS_PER_CLUSTER (CLUSTER_SIZE / ROWS_PER_BLOCK)   // 625

__global__ void k_scores(const float* __restrict__ h1,
                         const float* __restrict__ h2,
                         const void* __restrict__ ci,
                         const float* __restrict__ b_ptr) {
    int t    = threadIdx.x;
    int lane = t & 31;
    int wid  = t >> 5;
    int w    = blockIdx.x * ROWS_PER_BLOCK + wid;   // global row id
    int k    = blockIdx.x / BLOCKS_PER_CLUSTER;     // whole block same cluster

    __shared__ __align__(16) float wc_sh[HIDDEN];
    __shared__ float s_acc;
    wc_sh[t] = g_Wc[k][t];
    if (t == 0) s_acc = 0.0f;
    __syncthreads();

    long long row = (long long)load_idx(ci, w);

    const float4* r1 = (const float4*)(h1 + row * HIDDEN);
    const float4* r2 = (const float4*)(h2 + row * HIDDEN);
    const float4* wc = (const float4*)wc_sh;

    float4 c0 = wc[lane], c1 = wc[lane + 32];
    float4 a0 = r1[lane], a1 = r1[lane + 32];
    float4 b0 = r2[lane], b1 = r2[lane + 32];

    float s1 = dot4(a0, c0) + dot4(a1, c1);
    float s2 = dot4(b0, c0) + dot4(b1, c1);
    #pragma unroll
    for (int o = 16; o; o >>= 1) {
        s1 += __shfl_xor_sync(0xffffffffu, s1, o);
        s2 += __shfl_xor_sync(0xffffffffu, s2, o);
    }
    if (lane == 0) {
        float b = __ldg(b_ptr);
        float loss = softplus_f(-(s1 + b)) + softplus_f(s2 + b);
        atomicAdd(&s_acc, loss);
    }
    __syncthreads();
    if (t == 0) atomicAdd(&g_total, s_acc);
}

// ---------------------------------------------------------------------------
// Kernel 4: finalize   loss = 0.5/(K*n) * total
// ---------------------------------------------------------------------------
__global__ void k_finalize(float* __restrict__ out) {
    out[0] = 0.5f * g_total / (float)N_ROWS;
}

// ---------------------------------------------------------------------------
extern "C" void kernel_launch(void* const* d_in, const int* in_sizes, int n_in,
                              void* d_out, int out_size) {
    const float* h1 = (const float*)d_in[0];
    const float* h2 = (const float*)d_in[1];
    const void*  ci = d_in[2];
    const float* W  = (const float*)d_in[3];
    const float* b  = (const float*)d_in[4];
    float*      out = (float*)d_out;

    k_setup<<<K_CLUSTERS, 256>>>((const int*)ci);
    k_gather_sum<<<K_CLUSTERS * CHUNKS, 256>>>(h1, ci);
    k_wc<<<K_CLUSTERS * 32, 256>>>(W);
    k_scores<<<N_ROWS / ROWS_PER_BLOCK, 256>>>(h1, h2, ci, b);
    k_finalize<<<1, 1>>>(out);
}